// round 3
// baseline (speedup 1.0000x reference)
#include <cuda_runtime.h>
#include <cstdint>

#define BB 4
#define NN 8192
#define KK 16
#define O1 64
#define HH 128
#define TOT (BB*NN)
#define BN_EPS 1e-5f
#define NORM_EPSF 1e-12f
#define SLOPE 0.2f

// ---------------- scratch (static device globals; no allocation) ----------------
__device__ float  d_cent[BB][3];
__device__ float  d_g[BB][NN];
__device__ float  d_gcn[BB][NN][3];        // normalized p2gc, point-major
__device__ double d_sstat[4];              // g sum, g sumsq, alpha sum, alpha sumsq
__device__ float  d_amin[BB][NN];
__device__ float  d_amax[BB][NN];
__device__ float  d_pre[2][BB][HH][NN];    // pre-BN layer2 outputs (dis, ang)
__device__ double d_cstat[4][HH];          // per-channel sum/sumsq for layer2 BN

// ---------------- K0: zero scalar accumulators ----------------
__global__ void k_zero() {
    if (threadIdx.x < 4) d_sstat[threadIdx.x] = 0.0;
}

// ---------------- K1: centroid per (batch, coord) ----------------
__global__ void k_centroid(const float* __restrict__ pts) {
    int b = blockIdx.x / 3, c = blockIdx.x % 3;
    const float* p = pts + (b * 3 + c) * NN;
    float s = 0.f;
    for (int n = threadIdx.x; n < NN; n += 256) s += p[n];
    __shared__ float sm[256];
    sm[threadIdx.x] = s; __syncthreads();
    for (int o = 128; o; o >>= 1) {
        if (threadIdx.x < o) sm[threadIdx.x] += sm[threadIdx.x + o];
        __syncthreads();
    }
    if (threadIdx.x == 0) d_cent[b][c] = sm[0] * (1.f / NN);
}

// ---------------- K2: g = |p - centroid|^2, normalized p2gc, g stats ----------------
__global__ void k_prep(const float* __restrict__ pts) {
    int i = blockIdx.x * 256 + threadIdx.x;
    int b = i >> 13, n = i & (NN - 1);
    float vx = pts[(b * 3 + 0) * NN + n] - d_cent[b][0];
    float vy = pts[(b * 3 + 1) * NN + n] - d_cent[b][1];
    float vz = pts[(b * 3 + 2) * NN + n] - d_cent[b][2];
    float g = vx * vx + vy * vy + vz * vz;
    d_g[b][n] = g;
    float inv = 1.f / fmaxf(sqrtf(g), NORM_EPSF);
    d_gcn[b][n][0] = vx * inv;
    d_gcn[b][n][1] = vy * inv;
    d_gcn[b][n][2] = vz * inv;

    __shared__ float s1[256], s2[256];
    s1[threadIdx.x] = g; s2[threadIdx.x] = g * g;
    __syncthreads();
    for (int o = 128; o; o >>= 1) {
        if (threadIdx.x < o) { s1[threadIdx.x] += s1[threadIdx.x + o]; s2[threadIdx.x] += s2[threadIdx.x + o]; }
        __syncthreads();
    }
    if (threadIdx.x == 0) {
        atomicAdd(&d_sstat[0], (double)s1[0]);
        atomicAdd(&d_sstat[1], (double)s2[0]);
    }
}

// ---------------- K3: brute-force kNN (top-16) + alpha min/max + alpha stats ----------------
__global__ void __launch_bounds__(256) k_knn(const float* __restrict__ pts) {
    int b = blockIdx.x >> 5;
    int qn = ((blockIdx.x & 31) << 8) | threadIdx.x;
    const float* px = pts + (size_t)b * 3 * NN;
    const float* py = px + NN;
    const float* pz = py + NN;
    float qx = px[qn], qy = py[qn], qz = pz[qn];

    __shared__ float4 tile[256];
    float nd[KK]; int ni[KK];
#pragma unroll
    for (int s = 0; s < KK; s++) { nd[s] = 3.4e38f; ni[s] = 0; }
    float worst = 3.4e38f; int wslot = 0;

    for (int t = 0; t < NN / 256; t++) {
        __syncthreads();
        int j = (t << 8) | threadIdx.x;
        float cx = px[j], cy = py[j], cz = pz[j];
        tile[threadIdx.x] = make_float4(cx, cy, cz, fmaf(cx, cx, fmaf(cy, cy, cz * cz)));
        __syncthreads();
#pragma unroll 4
        for (int jj = 0; jj < 256; jj++) {
            float4 c = tile[jj];
            float inner = fmaf(qx, c.x, fmaf(qy, c.y, qz * c.z));
            float key = fmaf(-2.f, inner, c.w);   // = d_ij - |q|^2 (same ordering)
            if (key < worst) {
                int gj = (t << 8) | jj;
#pragma unroll
                for (int s = 0; s < KK; s++) if (s == wslot) { nd[s] = key; ni[s] = gj; }
                worst = nd[0]; wslot = 0;
#pragma unroll
                for (int s = 1; s < KK; s++) if (nd[s] > worst) { worst = nd[s]; wslot = s; }
            }
        }
    }

    // epilogue: alpha for the 16 kept neighbors (self gives alpha = 0 exactly)
    float gx = d_gcn[b][qn][0], gy = d_gcn[b][qn][1], gz = d_gcn[b][qn][2];
    float amin = 3.4e38f, amax = -3.4e38f, asum = 0.f, asq = 0.f;
#pragma unroll
    for (int s = 0; s < KK; s++) {
        int j = ni[s];
        float vx = px[j] - qx, vy = py[j] - qy, vz = pz[j] - qz;
        float inv = 1.f / fmaxf(sqrtf(fmaf(vx, vx, fmaf(vy, vy, vz * vz))), NORM_EPSF);
        float al = fmaf(vx, gx, fmaf(vy, gy, vz * gz)) * inv;
        amin = fminf(amin, al); amax = fmaxf(amax, al);
        asum += al; asq = fmaf(al, al, asq);
    }
    d_amin[b][qn] = amin; d_amax[b][qn] = amax;

    __shared__ float s1[256], s2[256];
    s1[threadIdx.x] = asum; s2[threadIdx.x] = asq;
    __syncthreads();
    for (int o = 128; o; o >>= 1) {
        if (threadIdx.x < o) { s1[threadIdx.x] += s1[threadIdx.x + o]; s2[threadIdx.x] += s2[threadIdx.x + o]; }
        __syncthreads();
    }
    if (threadIdx.x == 0) {
        atomicAdd(&d_sstat[2], (double)s1[0]);
        atomicAdd(&d_sstat[3], (double)s2[0]);
    }
}

// ---------------- K4: per-point 64-ch activation + 64->128 matvec (both branches) ----------------
__global__ void __launch_bounds__(256) k_mlp(
    const float* __restrict__ W1d, const float* __restrict__ G1d, const float* __restrict__ B1d,
    const float* __restrict__ W2d,
    const float* __restrict__ W1a, const float* __restrict__ G1a, const float* __restrict__ B1a,
    const float* __restrict__ W2a) {
    __shared__ float sS[O1], sT[O1];
    __shared__ __align__(16) float sW[HH * O1];
    int tid = threadIdx.x;
    int i = blockIdx.x * 256 + tid;
    int b = i >> 13, n = i & (NN - 1);
    float gval = d_g[b][n];
    float amin = d_amin[b][n], amax = d_amax[b][n];

#pragma unroll
    for (int br = 0; br < 2; br++) {
        __syncthreads();
        double cnt = br ? (double)TOT * KK : (double)TOT;
        double mu = d_sstat[2 * br] / cnt;
        float vg = (float)(d_sstat[2 * br + 1] / cnt - mu * mu);
        float mg = (float)mu;
        const float* W1 = br ? W1a : W1d;
        const float* G1 = br ? G1a : G1d;
        const float* B1 = br ? B1a : B1d;
        const float* W2 = br ? W2a : W2d;
        if (tid < O1) {
            float w = W1[tid];
            float sc = w * G1[tid] * rsqrtf(fmaf(w * w, vg, BN_EPS));
            sS[tid] = sc;
            sT[tid] = fmaf(-mg, sc, B1[tid]);
        }
        for (int x = tid; x < HH * O1 / 4; x += 256)
            reinterpret_cast<float4*>(sW)[x] = reinterpret_cast<const float4*>(W2)[x];
        __syncthreads();

        // layer-1 activations. ang branch: max over k collapses to amin/amax by monotonicity.
        float act[O1];
#pragma unroll
        for (int o = 0; o < O1; o++) {
            float s = sS[o];
            float x = br ? (s >= 0.f ? amax : amin) : gval;
            float y = fmaf(x, s, sT[o]);
            act[o] = y >= 0.f ? y : SLOPE * y;
        }

        float* pre = &d_pre[br][b][0][n];
        for (int h0 = 0; h0 < HH; h0 += 4) {
            float a0 = 0.f, a1 = 0.f, a2 = 0.f, a3 = 0.f;
#pragma unroll
            for (int o = 0; o < O1; o += 4) {
                float4 w0 = *reinterpret_cast<const float4*>(&sW[(h0 + 0) * O1 + o]);
                float4 w1 = *reinterpret_cast<const float4*>(&sW[(h0 + 1) * O1 + o]);
                float4 w2 = *reinterpret_cast<const float4*>(&sW[(h0 + 2) * O1 + o]);
                float4 w3 = *reinterpret_cast<const float4*>(&sW[(h0 + 3) * O1 + o]);
                a0 = fmaf(w0.x, act[o], fmaf(w0.y, act[o + 1], fmaf(w0.z, act[o + 2], fmaf(w0.w, act[o + 3], a0))));
                a1 = fmaf(w1.x, act[o], fmaf(w1.y, act[o + 1], fmaf(w1.z, act[o + 2], fmaf(w1.w, act[o + 3], a1))));
                a2 = fmaf(w2.x, act[o], fmaf(w2.y, act[o + 1], fmaf(w2.z, act[o + 2], fmaf(w2.w, act[o + 3], a2))));
                a3 = fmaf(w3.x, act[o], fmaf(w3.y, act[o + 1], fmaf(w3.z, act[o + 2], fmaf(w3.w, act[o + 3], a3))));
            }
            pre[(h0 + 0) * NN] = a0;
            pre[(h0 + 1) * NN] = a1;
            pre[(h0 + 2) * NN] = a2;
            pre[(h0 + 3) * NN] = a3;
        }
    }
}

// ---------------- K4b: per-channel BN stats for layer 2 (coalesced, one block/channel) ----------------
__global__ void k_cstat() {
    int br = blockIdx.x >> 7;
    int h = blockIdx.x & 127;
    float s = 0.f, q = 0.f;
    for (int bb = 0; bb < BB; bb++) {
        const float* row = &d_pre[br][bb][h][0];
        for (int n = threadIdx.x; n < NN; n += 256) {
            float v = row[n];
            s += v; q = fmaf(v, v, q);
        }
    }
    __shared__ float s1[256], s2[256];
    s1[threadIdx.x] = s; s2[threadIdx.x] = q;
    __syncthreads();
    for (int o = 128; o; o >>= 1) {
        if (threadIdx.x < o) { s1[threadIdx.x] += s1[threadIdx.x + o]; s2[threadIdx.x] += s2[threadIdx.x + o]; }
        __syncthreads();
    }
    if (threadIdx.x == 0) {
        d_cstat[2 * br][h] = (double)s1[0];
        d_cstat[2 * br + 1][h] = (double)s2[0];
    }
}

// ---------------- K5: final BN + LeakyReLU + concat write ----------------
__global__ void k_out(const float* __restrict__ G2d, const float* __restrict__ B2d,
                      const float* __restrict__ G2a, const float* __restrict__ B2a,
                      float* __restrict__ out) {
    __shared__ float sc[2 * HH], sh[2 * HH];
    int tid = threadIdx.x;
    if (tid < 2 * HH) {
        int br = tid >> 7, h = tid & 127;
        double mu = d_cstat[2 * br][h] / TOT;
        float var = (float)(d_cstat[2 * br + 1][h] / TOT - mu * mu);
        float gam = br ? G2a[h] : G2d[h];
        float bet = br ? B2a[h] : B2d[h];
        float s = gam * rsqrtf(var + BN_EPS);
        sc[tid] = s;
        sh[tid] = fmaf(-(float)mu, s, bet);
    }
    __syncthreads();
    const int total = BB * 2 * HH * NN;
    for (int idx = blockIdx.x * 256 + tid; idx < total; idx += gridDim.x * 256) {
        int b = idx >> 21;
        int c = (idx >> 13) & 255;
        int n = idx & (NN - 1);
        float v = d_pre[c >> 7][b][c & 127][n];
        float y = fmaf(v, sc[c], sh[c]);
        out[idx] = y >= 0.f ? y : SLOPE * y;
    }
}

// ---------------- launcher ----------------
extern "C" void kernel_launch(void* const* d_in, const int* in_sizes, int n_in,
                              void* d_out, int out_size) {
    const float* pts = (const float*)d_in[0];
    // input 1 should be the scalar k; if it's missing, weights start at index 1.
    int base = 2;
    if (n_in >= 2 && in_sizes[1] > 1) base = 1;
    const float* W1d = (const float*)d_in[base + 0];
    const float* G1d = (const float*)d_in[base + 1];
    const float* B1d = (const float*)d_in[base + 2];
    const float* W2d = (const float*)d_in[base + 3];
    const float* G2d = (const float*)d_in[base + 4];
    const float* B2d = (const float*)d_in[base + 5];
    const float* W1a = (const float*)d_in[base + 6];
    const float* G1a = (const float*)d_in[base + 7];
    const float* B1a = (const float*)d_in[base + 8];
    const float* W2a = (const float*)d_in[base + 9];
    const float* G2a = (const float*)d_in[base + 10];
    const float* B2a = (const float*)d_in[base + 11];
    float* out = (float*)d_out;

    k_zero<<<1, 32>>>();
    k_centroid<<<12, 256>>>(pts);
    k_prep<<<TOT / 256, 256>>>(pts);
    k_knn<<<TOT / 256, 256>>>(pts);
    k_mlp<<<TOT / 256, 256>>>(W1d, G1d, B1d, W2d, W1a, G1a, B1a, W2a);
    k_cstat<<<2 * HH, 256>>>();
    k_out<<<512, 256>>>(G2d, B2d, G2a, B2a, out);
}

// round 5
// speedup vs baseline: 2.3784x; 2.3784x over previous
#include <cuda_runtime.h>
#include <cstdint>

#define BB 4
#define NN 8192
#define KK 16
#define O1 64
#define HH 128
#define TOT (BB*NN)
#define BN_EPS 1e-5f
#define NORM_EPSF 1e-12f
#define SLOPE 0.2f

#define TPB 64          // threads per knn block
#define TILE 512        // candidates per smem tile
#define CAP 96          // survivor buffer capacity per thread

// ---------------- scratch (static device globals; no allocation) ----------------
__device__ float  d_cent[BB][3];
__device__ float  d_g[BB][NN];
__device__ float  d_gcn[BB][NN][3];        // normalized p2gc, point-major
__device__ float4 d_pts4[BB][NN];          // packed (x,y,z,|p|^2)
__device__ double d_sstat[4];              // g sum, g sumsq, alpha sum, alpha sumsq
__device__ float  d_amin[BB][NN];
__device__ float  d_amax[BB][NN];
__device__ float  d_pre[2][BB][HH][NN];    // pre-BN layer2 outputs (dis, ang)
__device__ double d_cstat[4][HH];          // per-channel sum/sumsq for layer2 BN

// ---------------- K0: zero scalar accumulators ----------------
__global__ void k_zero() {
    if (threadIdx.x < 4) d_sstat[threadIdx.x] = 0.0;
}

// ---------------- K1: centroid per (batch, coord) ----------------
__global__ void k_centroid(const float* __restrict__ pts) {
    int b = blockIdx.x / 3, c = blockIdx.x % 3;
    const float* p = pts + (b * 3 + c) * NN;
    float s = 0.f;
    for (int n = threadIdx.x; n < NN; n += 256) s += p[n];
    __shared__ float sm[256];
    sm[threadIdx.x] = s; __syncthreads();
    for (int o = 128; o; o >>= 1) {
        if (threadIdx.x < o) sm[threadIdx.x] += sm[threadIdx.x + o];
        __syncthreads();
    }
    if (threadIdx.x == 0) d_cent[b][c] = sm[0] * (1.f / NN);
}

// ---------------- K2: g, normalized p2gc, g stats, packed pts4 ----------------
__global__ void k_prep(const float* __restrict__ pts) {
    int i = blockIdx.x * 256 + threadIdx.x;
    int b = i >> 13, n = i & (NN - 1);
    float x = pts[(b * 3 + 0) * NN + n];
    float y = pts[(b * 3 + 1) * NN + n];
    float z = pts[(b * 3 + 2) * NN + n];
    // same formula as the knn key's |c|^2 term (bit-identical ordering)
    d_pts4[b][n] = make_float4(x, y, z, fmaf(x, x, fmaf(y, y, z * z)));

    float vx = x - d_cent[b][0];
    float vy = y - d_cent[b][1];
    float vz = z - d_cent[b][2];
    float g = vx * vx + vy * vy + vz * vz;
    d_g[b][n] = g;
    float inv = 1.f / fmaxf(sqrtf(g), NORM_EPSF);
    d_gcn[b][n][0] = vx * inv;
    d_gcn[b][n][1] = vy * inv;
    d_gcn[b][n][2] = vz * inv;

    __shared__ float s1[256], s2[256];
    s1[threadIdx.x] = g; s2[threadIdx.x] = g * g;
    __syncthreads();
    for (int o = 128; o; o >>= 1) {
        if (threadIdx.x < o) { s1[threadIdx.x] += s1[threadIdx.x + o]; s2[threadIdx.x] += s2[threadIdx.x + o]; }
        __syncthreads();
    }
    if (threadIdx.x == 0) {
        atomicAdd(&d_sstat[0], (double)s1[0]);
        atomicAdd(&d_sstat[1], (double)s2[0]);
    }
}

// ---------------- K3: kNN via threshold-filter (branchless scans) ----------------
__global__ void __launch_bounds__(TPB) k_knn() {
    int b = blockIdx.x >> 7;                               // 128 blocks per batch
    int qn = ((blockIdx.x & 127) << 6) | threadIdx.x;
    const float4* __restrict__ P = &d_pts4[b][0];
    __shared__ float4 tile[TILE];
    __shared__ int sbuf[CAP][TPB];                         // [slot][lane]: conflict-free
    float4 q = P[qn];

    // ---- pass 1: 32 interleaved partition minima (branchless) ----
    float m[32];
#pragma unroll
    for (int i = 0; i < 32; i++) m[i] = 3.4e38f;

    for (int t = 0; t < NN / TILE; t++) {
        __syncthreads();
#pragma unroll
        for (int r = 0; r < TILE / TPB; r++)
            tile[r * TPB + threadIdx.x] = P[t * TILE + r * TPB + threadIdx.x];
        __syncthreads();
#pragma unroll 32
        for (int jj = 0; jj < TILE; jj++) {
            float4 c = tile[jj];
            float key = fmaf(-2.f, fmaf(q.x, c.x, fmaf(q.y, c.y, q.z * c.z)), c.w);
            m[jj & 31] = fminf(m[jj & 31], key);
        }
    }

    // tau = 16th smallest of the 32 partition minima (>= true 16th-smallest key).
    // Full bitonic sort, ascending; all indices static after unroll.
#pragma unroll
    for (int kk = 2; kk <= 32; kk <<= 1) {
#pragma unroll
        for (int j = kk >> 1; j > 0; j >>= 1) {
#pragma unroll
            for (int i = 0; i < 32; i++) {
                int ixj = i ^ j;
                if (ixj > i) {
                    bool up = ((i & kk) == 0);
                    float lo = fminf(m[i], m[ixj]);
                    float hi = fmaxf(m[i], m[ixj]);
                    m[i]   = up ? lo : hi;
                    m[ixj] = up ? hi : lo;
                }
            }
        }
    }
    float tau = m[15];

    // ---- pass 2: collect survivor indices (branchless unconditional-store) ----
    int cnt = 0;
    for (int t = 0; t < NN / TILE; t++) {
        __syncthreads();
#pragma unroll
        for (int r = 0; r < TILE / TPB; r++)
            tile[r * TPB + threadIdx.x] = P[t * TILE + r * TPB + threadIdx.x];
        __syncthreads();
        int jb = t * TILE;
#pragma unroll 16
        for (int jj = 0; jj < TILE; jj++) {
            float4 c = tile[jj];
            float key = fmaf(-2.f, fmaf(q.x, c.x, fmaf(q.y, c.y, q.z * c.z)), c.w);
            int idx = cnt < CAP ? cnt : CAP - 1;
            sbuf[idx][threadIdx.x] = jb + jj;          // kept only if accepted (cnt advances)
            cnt += (key <= tau) ? 1 : 0;
        }
    }

    // ---- exact top-16 over the ~22-40 survivors (ascending j order => same ties) ----
    float nd[KK]; int ni[KK];
#pragma unroll
    for (int s = 0; s < KK; s++) { nd[s] = 3.4e38f; ni[s] = 0; }
    float worst = 3.4e38f; int wslot = 0;
    int c2 = cnt < CAP ? cnt : CAP;
    for (int i = 0; i < c2; i++) {
        int j = sbuf[i][threadIdx.x];
        float4 c = __ldg(&P[j]);
        float key = fmaf(-2.f, fmaf(q.x, c.x, fmaf(q.y, c.y, q.z * c.z)), c.w);
        if (key < worst) {
#pragma unroll
            for (int s = 0; s < KK; s++) if (s == wslot) { nd[s] = key; ni[s] = j; }
            worst = nd[0]; wslot = 0;
#pragma unroll
            for (int s = 1; s < KK; s++) if (nd[s] > worst) { worst = nd[s]; wslot = s; }
        }
    }

    // safety fallback (P ~ 1e-13): exact rescan if buffer overflowed
    if (cnt > CAP) {
#pragma unroll
        for (int s = 0; s < KK; s++) { nd[s] = 3.4e38f; ni[s] = 0; }
        worst = 3.4e38f; wslot = 0;
        for (int j = 0; j < NN; j++) {
            float4 c = __ldg(&P[j]);
            float key = fmaf(-2.f, fmaf(q.x, c.x, fmaf(q.y, c.y, q.z * c.z)), c.w);
            if (key < worst) {
#pragma unroll
                for (int s = 0; s < KK; s++) if (s == wslot) { nd[s] = key; ni[s] = j; }
                worst = nd[0]; wslot = 0;
#pragma unroll
                for (int s = 1; s < KK; s++) if (nd[s] > worst) { worst = nd[s]; wslot = s; }
            }
        }
    }

    // ---- epilogue: alpha over the 16 kept neighbors ----
    float gx = d_gcn[b][qn][0], gy = d_gcn[b][qn][1], gz = d_gcn[b][qn][2];
    float amin = 3.4e38f, amax = -3.4e38f, asum = 0.f, asq = 0.f;
#pragma unroll
    for (int s = 0; s < KK; s++) {
        int j = ni[s];
        float4 c = __ldg(&P[j]);
        float vx = c.x - q.x, vy = c.y - q.y, vz = c.z - q.z;
        float inv = 1.f / fmaxf(sqrtf(fmaf(vx, vx, fmaf(vy, vy, vz * vz))), NORM_EPSF);
        float al = fmaf(vx, gx, fmaf(vy, gy, vz * gz)) * inv;
        amin = fminf(amin, al); amax = fmaxf(amax, al);
        asum += al; asq = fmaf(al, al, asq);
    }
    d_amin[b][qn] = amin; d_amax[b][qn] = amax;

    __shared__ float s1[TPB], s2[TPB];
    s1[threadIdx.x] = asum; s2[threadIdx.x] = asq;
    __syncthreads();
    for (int o = TPB / 2; o; o >>= 1) {
        if (threadIdx.x < o) { s1[threadIdx.x] += s1[threadIdx.x + o]; s2[threadIdx.x] += s2[threadIdx.x + o]; }
        __syncthreads();
    }
    if (threadIdx.x == 0) {
        atomicAdd(&d_sstat[2], (double)s1[0]);
        atomicAdd(&d_sstat[3], (double)s2[0]);
    }
}

// ---------------- K4: per-point 64-ch activation + 64->128 matvec (both branches) ----------------
__global__ void __launch_bounds__(256) k_mlp(
    const float* __restrict__ W1d, const float* __restrict__ G1d, const float* __restrict__ B1d,
    const float* __restrict__ W2d,
    const float* __restrict__ W1a, const float* __restrict__ G1a, const float* __restrict__ B1a,
    const float* __restrict__ W2a) {
    __shared__ float sS[O1], sT[O1];
    __shared__ __align__(16) float sW[HH * O1];
    int tid = threadIdx.x;
    int i = blockIdx.x * 256 + tid;
    int b = i >> 13, n = i & (NN - 1);
    float gval = d_g[b][n];
    float amin = d_amin[b][n], amax = d_amax[b][n];

#pragma unroll
    for (int br = 0; br < 2; br++) {
        __syncthreads();
        double cnt = br ? (double)TOT * KK : (double)TOT;
        double mu = d_sstat[2 * br] / cnt;
        float vg = (float)(d_sstat[2 * br + 1] / cnt - mu * mu);
        float mg = (float)mu;
        const float* W1 = br ? W1a : W1d;
        const float* G1 = br ? G1a : G1d;
        const float* B1 = br ? B1a : B1d;
        const float* W2 = br ? W2a : W2d;
        if (tid < O1) {
            float w = W1[tid];
            float sc = w * G1[tid] * rsqrtf(fmaf(w * w, vg, BN_EPS));
            sS[tid] = sc;
            sT[tid] = fmaf(-mg, sc, B1[tid]);
        }
        for (int x = tid; x < HH * O1 / 4; x += 256)
            reinterpret_cast<float4*>(sW)[x] = reinterpret_cast<const float4*>(W2)[x];
        __syncthreads();

        float act[O1];
#pragma unroll
        for (int o = 0; o < O1; o++) {
            float s = sS[o];
            float x = br ? (s >= 0.f ? amax : amin) : gval;
            float y = fmaf(x, s, sT[o]);
            act[o] = y >= 0.f ? y : SLOPE * y;
        }

        float* pre = &d_pre[br][b][0][n];
        for (int h0 = 0; h0 < HH; h0 += 4) {
            float a0 = 0.f, a1 = 0.f, a2 = 0.f, a3 = 0.f;
#pragma unroll
            for (int o = 0; o < O1; o += 4) {
                float4 w0 = *reinterpret_cast<const float4*>(&sW[(h0 + 0) * O1 + o]);
                float4 w1 = *reinterpret_cast<const float4*>(&sW[(h0 + 1) * O1 + o]);
                float4 w2 = *reinterpret_cast<const float4*>(&sW[(h0 + 2) * O1 + o]);
                float4 w3 = *reinterpret_cast<const float4*>(&sW[(h0 + 3) * O1 + o]);
                a0 = fmaf(w0.x, act[o], fmaf(w0.y, act[o + 1], fmaf(w0.z, act[o + 2], fmaf(w0.w, act[o + 3], a0))));
                a1 = fmaf(w1.x, act[o], fmaf(w1.y, act[o + 1], fmaf(w1.z, act[o + 2], fmaf(w1.w, act[o + 3], a1))));
                a2 = fmaf(w2.x, act[o], fmaf(w2.y, act[o + 1], fmaf(w2.z, act[o + 2], fmaf(w2.w, act[o + 3], a2))));
                a3 = fmaf(w3.x, act[o], fmaf(w3.y, act[o + 1], fmaf(w3.z, act[o + 2], fmaf(w3.w, act[o + 3], a3))));
            }
            pre[(h0 + 0) * NN] = a0;
            pre[(h0 + 1) * NN] = a1;
            pre[(h0 + 2) * NN] = a2;
            pre[(h0 + 3) * NN] = a3;
        }
    }
}

// ---------------- K4b: per-channel BN stats for layer 2 ----------------
__global__ void k_cstat() {
    int br = blockIdx.x >> 7;
    int h = blockIdx.x & 127;
    float s = 0.f, q = 0.f;
    for (int bb = 0; bb < BB; bb++) {
        const float* row = &d_pre[br][bb][h][0];
        for (int n = threadIdx.x; n < NN; n += 256) {
            float v = row[n];
            s += v; q = fmaf(v, v, q);
        }
    }
    __shared__ float s1[256], s2[256];
    s1[threadIdx.x] = s; s2[threadIdx.x] = q;
    __syncthreads();
    for (int o = 128; o; o >>= 1) {
        if (threadIdx.x < o) { s1[threadIdx.x] += s1[threadIdx.x + o]; s2[threadIdx.x] += s2[threadIdx.x + o]; }
        __syncthreads();
    }
    if (threadIdx.x == 0) {
        d_cstat[2 * br][h] = (double)s1[0];
        d_cstat[2 * br + 1][h] = (double)s2[0];
    }
}

// ---------------- K5: final BN + LeakyReLU + concat write ----------------
__global__ void k_out(const float* __restrict__ G2d, const float* __restrict__ B2d,
                      const float* __restrict__ G2a, const float* __restrict__ B2a,
                      float* __restrict__ out) {
    __shared__ float sc[2 * HH], sh[2 * HH];
    int tid = threadIdx.x;
    if (tid < 2 * HH) {
        int br = tid >> 7, h = tid & 127;
        double mu = d_cstat[2 * br][h] / TOT;
        float var = (float)(d_cstat[2 * br + 1][h] / TOT - mu * mu);
        float gam = br ? G2a[h] : G2d[h];
        float bet = br ? B2a[h] : B2d[h];
        float s = gam * rsqrtf(var + BN_EPS);
        sc[tid] = s;
        sh[tid] = fmaf(-(float)mu, s, bet);
    }
    __syncthreads();
    const int total = BB * 2 * HH * NN;
    for (int idx = blockIdx.x * 256 + tid; idx < total; idx += gridDim.x * 256) {
        int b = idx >> 21;
        int c = (idx >> 13) & 255;
        int n = idx & (NN - 1);
        float v = d_pre[c >> 7][b][c & 127][n];
        float y = fmaf(v, sc[c], sh[c]);
        out[idx] = y >= 0.f ? y : SLOPE * y;
    }
}

// ---------------- launcher ----------------
extern "C" void kernel_launch(void* const* d_in, const int* in_sizes, int n_in,
                              void* d_out, int out_size) {
    const float* pts = (const float*)d_in[0];
    int base = 2;
    if (n_in >= 2 && in_sizes[1] > 1) base = 1;
    const float* W1d = (const float*)d_in[base + 0];
    const float* G1d = (const float*)d_in[base + 1];
    const float* B1d = (const float*)d_in[base + 2];
    const float* W2d = (const float*)d_in[base + 3];
    const float* G2d = (const float*)d_in[base + 4];
    const float* B2d = (const float*)d_in[base + 5];
    const float* W1a = (const float*)d_in[base + 6];
    const float* G1a = (const float*)d_in[base + 7];
    const float* B1a = (const float*)d_in[base + 8];
    const float* W2a = (const float*)d_in[base + 9];
    const float* G2a = (const float*)d_in[base + 10];
    const float* B2a = (const float*)d_in[base + 11];
    float* out = (float*)d_out;

    k_zero<<<1, 32>>>();
    k_centroid<<<12, 256>>>(pts);
    k_prep<<<TOT / 256, 256>>>(pts);
    k_knn<<<TOT / TPB, TPB>>>();
    k_mlp<<<TOT / 256, 256>>>(W1d, G1d, B1d, W2d, W1a, G1a, B1a, W2a);
    k_cstat<<<2 * HH, 256>>>();
    k_out<<<512, 256>>>(G2d, B2d, G2a, B2a, out);
}